// round 15
// baseline (speedup 1.0000x reference)
#include <cuda_runtime.h>
#include <cuda_fp16.h>
#include <cstdint>

// ---------------- problem constants ----------------
#define NB   2
#define LQ   17821
#define CC   256
#define HD   8
#define LL   4
#define PP   4
#define DD   32
#define LIN  17821
#define MROWS (NB*LQ)      // 35642
#define NTILES 279         // ceil(MROWS/128)
#define NCHUNK 4

__constant__ int c_H[LL]  = {100, 50, 25, 13};
__constant__ int c_W[LL]  = {134, 67, 34, 17};
__constant__ int c_S[LL]  = {0, 13400, 16750, 17600};

// ---------------- scratch ----------------
__device__ __half g_qh [(size_t)MROWS * CC];
__device__ __half g_xh [(size_t)MROWS * CC];
__device__ __half g_wv [256 * 256];
__device__ __half g_wofatt[256 * 384];        // Woff | Watt
__device__ __half g_wout[256 * 256];
__device__ __half g_val [(size_t)MROWS * CC];
__device__ float  g_oa  [(size_t)MROWS * 384]; // off (0-255) | att logits (256-383)
__device__ __half g_core[(size_t)MROWS * CC];

// ---------------- weight conversion ----------------
__global__ void convert_w_kernel(
    const float4* __restrict__ wvf,  const float4* __restrict__ woutf,
    const float4* __restrict__ wofff,const float4* __restrict__ wattf,
    __half2* __restrict__ wvh, __half2* __restrict__ wouth,
    __half2* __restrict__ wofatt)
{
    const int i = blockIdx.x * blockDim.x + threadIdx.x;
    const int seg = blockIdx.y;
    auto cvt = [](float4 v, __half2* d) {
        d[0] = __floats2half2_rn(v.x, v.y);
        d[1] = __floats2half2_rn(v.z, v.w);
    };
    if (seg == 0) {
        if (i < 16384) cvt(wvf[i], wvh + 2 * i);
    } else if (seg == 1) {
        if (i < 16384) cvt(woutf[i], wouth + 2 * i);
    } else if (seg == 2) {
        if (i < 16384) {
            int k = i >> 6, j = (i & 63) * 4;
            cvt(wofff[i], wofatt + (k * 384 + j) / 2);
        }
    } else {
        if (i < 8192) {
            int k = i >> 5, j = (i & 31) * 4;
            cvt(wattf[i], wofatt + (k * 384 + 256 + j) / 2);
        }
    }
}

// ---------------- single-tensor fp32->fp16 conversion ----------------
__global__ void convert_one_kernel(
    const float4* __restrict__ src, __half2* __restrict__ dst, int n4)
{
    const int i = blockIdx.x * blockDim.x + threadIdx.x;
    if (i >= n4) return;
    float4 v = src[i];
    dst[2 * i + 0] = __floats2half2_rn(v.x, v.y);
    dst[2 * i + 1] = __floats2half2_rn(v.z, v.w);
}

// ================= fp16 tensor-core GEMM core =================
#define NSTAGE 5
#define STG    16384

__device__ __forceinline__ int a_swz(int r, int c) {
    return (r * 4 + (c ^ ((r >> 1) & 3))) * 16;
}
__device__ __forceinline__ int b_swz(int r, int c) {
    return (r * 16 + (c ^ (r & 7))) * 16;
}

template <bool HALF_OUT>
__device__ __forceinline__ void hgemm_body(
    int M, int Ncols, int mBase, int nBase,
    const __half* __restrict__ A, const __half* __restrict__ B,
    const float* __restrict__ bp, void* __restrict__ Cv,
    unsigned char* smem_raw)
{
    const int K = 256;

    const int tid  = threadIdx.x;
    const int lane = tid & 31;
    const int warp = tid >> 5;
    const int wm = warp & 1;
    const int wn = warp >> 1;

    const int rA  = tid >> 1;
    const int cA0 = (tid & 1) * 2;
    const int rB  = tid >> 3;
    const int cB0 = (tid & 7) * 2;
    const int aSz = ((mBase + rA) < M) ? 16 : 0;
    const __half* Ag = A + (size_t)(mBase + rA) * K;
    const __half* Bg = B + nBase;

    const uint32_t smem_base = (uint32_t)__cvta_generic_to_shared(smem_raw);

    float acc[4][4][4];
#pragma unroll
    for (int i = 0; i < 4; i++)
#pragma unroll
        for (int j = 0; j < 4; j++)
#pragma unroll
            for (int c = 0; c < 4; c++) acc[i][j][c] = 0.f;

    auto issue_stage = [&](int kt, int s) {
        const int kb = kt * 32;
        const uint32_t ab = smem_base + s * STG;
        const uint32_t bb = ab + 8192;
#pragma unroll
        for (int c = cA0; c < cA0 + 2; c++) {
            uint32_t d = ab + a_swz(rA, c);
            const void* src = Ag + kb + c * 8;
            asm volatile("cp.async.cg.shared.global [%0], [%1], 16, %2;\n"
                         :: "r"(d), "l"(src), "r"(aSz));
        }
#pragma unroll
        for (int c = cB0; c < cB0 + 2; c++) {
            uint32_t d = bb + b_swz(rB, c);
            const void* src = Bg + (size_t)(kb + rB) * Ncols + c * 8;
            asm volatile("cp.async.cg.shared.global [%0], [%1], 16;\n"
                         :: "r"(d), "l"(src));
        }
        asm volatile("cp.async.commit_group;\n");
    };

    issue_stage(0, 0);
    issue_stage(1, 1);
    issue_stage(2, 2);
    issue_stage(3, 3);

    const int NKT = K / 32;   // 8
    for (int kt = 0; kt < NKT; kt++) {
        const int s = kt % NSTAGE;
        asm volatile("cp.async.wait_group 3;\n");
        __syncthreads();
        const uint32_t ab = smem_base + s * STG;
        const uint32_t bb = ab + 8192;

#pragma unroll
        for (int ks = 0; ks < 2; ks++) {
            uint32_t afr[4][4], bfr[2][4];
#pragma unroll
            for (int i = 0; i < 4; i++) {
                int row = wm * 64 + i * 16 + (lane & 15);
                int c   = 2 * ks + (lane >> 4);
                uint32_t ad = ab + a_swz(row, c);
                asm volatile("ldmatrix.sync.aligned.m8n8.x4.shared.b16 {%0,%1,%2,%3}, [%4];\n"
                             : "=r"(afr[i][0]), "=r"(afr[i][1]), "=r"(afr[i][2]), "=r"(afr[i][3])
                             : "r"(ad));
            }
#pragma unroll
            for (int jj = 0; jj < 2; jj++) {
                int kr = ks * 16 + (lane & 15);
                int c  = wn * 4 + jj * 2 + (lane >> 4);
                uint32_t bd = bb + b_swz(kr, c);
                asm volatile("ldmatrix.sync.aligned.m8n8.x4.trans.shared.b16 {%0,%1,%2,%3}, [%4];\n"
                             : "=r"(bfr[jj][0]), "=r"(bfr[jj][1]), "=r"(bfr[jj][2]), "=r"(bfr[jj][3])
                             : "r"(bd));
            }
#pragma unroll
            for (int i = 0; i < 4; i++)
#pragma unroll
                for (int j = 0; j < 4; j++) {
                    uint32_t b0 = bfr[j >> 1][(j & 1) * 2 + 0];
                    uint32_t b1 = bfr[j >> 1][(j & 1) * 2 + 1];
                    asm volatile(
                        "mma.sync.aligned.m16n8k16.row.col.f32.f16.f16.f32 "
                        "{%0,%1,%2,%3}, {%4,%5,%6,%7}, {%8,%9}, {%0,%1,%2,%3};\n"
                        : "+f"(acc[i][j][0]), "+f"(acc[i][j][1]),
                          "+f"(acc[i][j][2]), "+f"(acc[i][j][3])
                        : "r"(afr[i][0]), "r"(afr[i][1]), "r"(afr[i][2]), "r"(afr[i][3]),
                          "r"(b0), "r"(b1));
                }
        }

        if (kt + 4 < NKT) issue_stage(kt + 4, (kt + 4) % NSTAGE);
        else asm volatile("cp.async.commit_group;\n");
    }

#pragma unroll
    for (int i = 0; i < 4; i++) {
        int r0 = mBase + wm * 64 + i * 16 + (lane >> 2);
        int r1 = r0 + 8;
#pragma unroll
        for (int j = 0; j < 4; j++) {
            int col = nBase + wn * 32 + j * 8 + (lane & 3) * 2;
            float b0 = bp[col], b1 = bp[col + 1];
            float v00 = acc[i][j][0] + b0, v01 = acc[i][j][1] + b1;
            float v10 = acc[i][j][2] + b0, v11 = acc[i][j][3] + b1;
            if (r0 < M) {
                if constexpr (HALF_OUT)
                    *reinterpret_cast<__half2*>((__half*)Cv + (size_t)r0 * Ncols + col) =
                        __floats2half2_rn(v00, v01);
                else
                    *reinterpret_cast<float2*>((float*)Cv + (size_t)r0 * Ncols + col) =
                        make_float2(v00, v01);
            }
            if (r1 < M) {
                if constexpr (HALF_OUT)
                    *reinterpret_cast<__half2*>((__half*)Cv + (size_t)r1 * Ncols + col) =
                        __floats2half2_rn(v10, v11);
                else
                    *reinterpret_cast<float2*>((float*)Cv + (size_t)r1 * Ncols + col) =
                        make_float2(v10, v11);
            }
        }
    }
}

// value GEMM (full M): xh @ wv + bv -> val (half out)
__global__ __launch_bounds__(256) void hgemm_val_kernel(
    const __half* __restrict__ xh, const __half* __restrict__ wv,
    const float*  __restrict__ bv, __half* __restrict__ val)
{
    extern __shared__ __align__(16) unsigned char smem_raw[];
    hgemm_body<true>(MROWS, 256, blockIdx.y * 128, blockIdx.x * 128,
                     xh, wv, bv, val, smem_raw);
}

// oa GEMM chunk: qh @ wofatt + (boff|batt) -> oa (float out, N=384)
__global__ __launch_bounds__(256) void hgemm_oa_kernel(
    const __half* __restrict__ qh, const __half* __restrict__ wofatt,
    const float* __restrict__ boff, const float* __restrict__ batt,
    float* __restrict__ oa, int tileBase)
{
    extern __shared__ __align__(16) unsigned char smem_raw[];
    const int nBase = blockIdx.x * 128;
    const float* bp = (nBase < 256) ? boff : (batt - 256);
    hgemm_body<false>(MROWS, 384, (tileBase + blockIdx.y) * 128, nBase,
                      qh, wofatt, bp, oa, smem_raw);
}

// out GEMM chunk
__global__ __launch_bounds__(256) void hgemm_out_kernel(
    const __half* __restrict__ core, const __half* __restrict__ wout,
    const float* __restrict__ bout, float* __restrict__ out, int tileBase)
{
    extern __shared__ __align__(16) unsigned char smem_raw[];
    hgemm_body<false>(MROWS, 256, (tileBase + blockIdx.y) * 128, blockIdx.x * 128,
                      core, wout, bout, out, smem_raw);
}

// ---------------- sampling: 4 lanes/unit, uint4 gathers, fused softmax -------
__global__ __launch_bounds__(256) void sample_kernel(
    const float* __restrict__ ref,
    const float* __restrict__ oa,
    const uint4* __restrict__ value,
    uint4*       __restrict__ core,
    int unitBase, int nUnits)
{
    const int t = blockIdx.x * blockDim.x + threadIdx.x;
    const int uLocal = t >> 2;
    const int l4     = t & 3;
    if (uLocal >= nUnits) return;
    const int unit = unitBase + uLocal;

    const int hd  = unit & (HD - 1);
    const int row = unit >> 3;
    const int n   = (row >= LQ) ? 1 : 0;

    const float* offr = oa + (size_t)row * 384 + hd * 32;
    const float* attr = oa + (size_t)row * 384 + 256 + hd * 16;
    const float* refr = ref + (size_t)row * 8;
    const uint4* vb = value + (size_t)n * (LIN * 32) + hd * 4 + l4;

    float w[16];
    float m = -1e30f;
#pragma unroll
    for (int i = 0; i < 16; i++) { w[i] = attr[i]; m = fmaxf(m, w[i]); }
    float s = 0.f;
#pragma unroll
    for (int i = 0; i < 16; i++) { w[i] = __expf(w[i] - m); s += w[i]; }
    const float inv = 1.f / s;

    float acc[8];
#pragma unroll
    for (int k = 0; k < 8; k++) acc[k] = 0.f;

#pragma unroll
    for (int l = 0; l < LL; l++) {
        const int H = c_H[l], W = c_W[l];
        const uint4* vlev = vb + (size_t)c_S[l] * 32;
        const float rx = refr[2 * l + 0];
        const float ry = refr[2 * l + 1];
#pragma unroll
        for (int p = 0; p < PP; p++) {
            const float ox = offr[(l * PP + p) * 2 + 0];
            const float oy = offr[(l * PP + p) * 2 + 1];
            const float aw = w[l * PP + p] * inv;
            const float x = rx * (float)W + ox - 0.5f;
            const float y = ry * (float)H + oy - 0.5f;
            const float xf = floorf(x), yf = floorf(y);
            const float fx = x - xf, fy = y - yf;
            const int x0 = (int)xf, y0 = (int)yf;
            const int x1 = x0 + 1,  y1 = y0 + 1;
            const float mx0 = (x0 >= 0 && x0 < W) ? 1.f : 0.f;
            const float mx1 = (x1 >= 0 && x1 < W) ? 1.f : 0.f;
            const float my0 = (y0 >= 0 && y0 < H) ? 1.f : 0.f;
            const float my1 = (y1 >= 0 && y1 < H) ? 1.f : 0.f;
            const int cx0 = min(max(x0, 0), W - 1);
            const int cx1 = min(max(x1, 0), W - 1);
            const int cy0 = min(max(y0, 0), H - 1);
            const int cy1 = min(max(y1, 0), H - 1);
            const float w00 = aw * (1.f - fx) * (1.f - fy) * mx0 * my0;
            const float w10 = aw * fx * (1.f - fy) * mx1 * my0;
            const float w01 = aw * (1.f - fx) * fy * mx0 * my1;
            const float w11 = aw * fx * fy * mx1 * my1;

            const uint4 v00 = vlev[(cy0 * W + cx0) * 32];
            const uint4 v10 = vlev[(cy0 * W + cx1) * 32];
            const uint4 v01 = vlev[(cy1 * W + cx0) * 32];
            const uint4 v11 = vlev[(cy1 * W + cx1) * 32];

            auto fmadd = [&](uint4 v, float wt) {
                float2 a = __half22float2(*reinterpret_cast<const __half2*>(&v.x));
                float2 b = __half22float2(*reinterpret_cast<const __half2*>(&v.y));
                float2 c = __half22float2(*reinterpret_cast<const __half2*>(&v.z));
                float2 d = __half22float2(*reinterpret_cast<const __half2*>(&v.w));
                acc[0] += wt * a.x; acc[1] += wt * a.y;
                acc[2] += wt * b.x; acc[3] += wt * b.y;
                acc[4] += wt * c.x; acc[5] += wt * c.y;
                acc[6] += wt * d.x; acc[7] += wt * d.y;
            };
            fmadd(v00, w00);
            fmadd(v10, w10);
            fmadd(v01, w01);
            fmadd(v11, w11);
        }
    }

    uint4 o;
    *reinterpret_cast<__half2*>(&o.x) = __floats2half2_rn(acc[0], acc[1]);
    *reinterpret_cast<__half2*>(&o.y) = __floats2half2_rn(acc[2], acc[3]);
    *reinterpret_cast<__half2*>(&o.z) = __floats2half2_rn(acc[4], acc[5]);
    *reinterpret_cast<__half2*>(&o.w) = __floats2half2_rn(acc[6], acc[7]);
    core[(size_t)row * 32 + hd * 4 + l4] = o;
}

// ---------------- launch: 2-stream pipeline with proper capture fork ---------
extern "C" void kernel_launch(void* const* d_in, const int* in_sizes, int n_in,
                              void* d_out, int out_size)
{
    const float* query = (const float*)d_in[0];
    const float* refpt = (const float*)d_in[1];
    const float* inflt = (const float*)d_in[2];
    const float* Wv    = (const float*)d_in[5];
    const float* bv    = (const float*)d_in[6];
    const float* Woff  = (const float*)d_in[7];
    const float* boff  = (const float*)d_in[8];
    const float* Watt  = (const float*)d_in[9];
    const float* batt  = (const float*)d_in[10];
    const float* Wout  = (const float*)d_in[11];
    const float* bout  = (const float*)d_in[12];
    float* out = (float*)d_out;

    __half *qh, *xh, *wv, *wofatt, *wout, *val, *core;
    float *oa;
    cudaGetSymbolAddress((void**)&qh,     g_qh);
    cudaGetSymbolAddress((void**)&xh,     g_xh);
    cudaGetSymbolAddress((void**)&wv,     g_wv);
    cudaGetSymbolAddress((void**)&wofatt, g_wofatt);
    cudaGetSymbolAddress((void**)&wout,   g_wout);
    cudaGetSymbolAddress((void**)&val,    g_val);
    cudaGetSymbolAddress((void**)&oa,     g_oa);
    cudaGetSymbolAddress((void**)&core,   g_core);

    const int SMEM = NSTAGE * STG;   // 80KB dynamic
    cudaFuncSetAttribute(hgemm_val_kernel,
                         cudaFuncAttributeMaxDynamicSharedMemorySize, SMEM);
    cudaFuncSetAttribute(hgemm_oa_kernel,
                         cudaFuncAttributeMaxDynamicSharedMemorySize, SMEM);
    cudaFuncSetAttribute(hgemm_out_kernel,
                         cudaFuncAttributeMaxDynamicSharedMemorySize, SMEM);

    // side stream + events (relaxed capture mode; no device allocation)
    cudaStream_t s1;
    cudaEvent_t eRoot, eQ, eF[NCHUNK], eS[NCHUNK];
    {
        cudaStreamCaptureMode mode = cudaStreamCaptureModeRelaxed;
        cudaThreadExchangeStreamCaptureMode(&mode);
        cudaStreamCreateWithFlags(&s1, cudaStreamNonBlocking);
        cudaEventCreateWithFlags(&eRoot, cudaEventDisableTiming);
        cudaEventCreateWithFlags(&eQ, cudaEventDisableTiming);
        for (int c = 0; c < NCHUNK; c++) {
            cudaEventCreateWithFlags(&eF[c], cudaEventDisableTiming);
            cudaEventCreateWithFlags(&eS[c], cudaEventDisableTiming);
        }
        cudaThreadExchangeStreamCaptureMode(&mode);   // restore
    }

    dim3 blk(256);
    const int TB[NCHUNK + 1] = {0, 70, 140, 210, NTILES};
    const int n4_all = MROWS * 64;   // float4 per 256-col row = 64

    // --- fork s1 from the capturing stream (stream 0) ---
    cudaEventRecord(eRoot, 0);
    cudaStreamWaitEvent(s1, eRoot, 0);

    // stream 1: convert query (overlaps value path below)
    convert_one_kernel<<<(n4_all + 255) / 256, blk, 0, s1>>>(
        (const float4*)query, (__half2*)qh, n4_all);
    cudaEventRecord(eQ, s1);

    // stream 0: weights, x, full value GEMM
    convert_w_kernel<<<dim3(64, 4), blk>>>(
        (const float4*)Wv, (const float4*)Wout,
        (const float4*)Woff, (const float4*)Watt,
        (__half2*)wv, (__half2*)wout, (__half2*)wofatt);
    convert_one_kernel<<<(n4_all + 255) / 256, blk>>>(
        (const float4*)inflt, (__half2*)xh, n4_all);
    hgemm_val_kernel<<<dim3(2, NTILES), blk, SMEM>>>(xh, wv, bv, val);

    // stream 0: oa GEMM chunks (need qh); eF[c] implies val complete (stream order)
    cudaStreamWaitEvent(0, eQ, 0);
    for (int c = 0; c < NCHUNK; c++) {
        const int t0 = TB[c], t1 = TB[c + 1];
        hgemm_oa_kernel<<<dim3(3, t1 - t0), blk, SMEM>>>(
            qh, wofatt, boff, batt, oa, t0);
        cudaEventRecord(eF[c], 0);
    }

    // stream 1: sampler chunks, gated on eF[c]
    for (int c = 0; c < NCHUNK; c++) {
        const int t0 = TB[c], t1 = TB[c + 1];
        const int r0 = t0 * 128;
        const int r1 = (t1 * 128 < MROWS) ? t1 * 128 : MROWS;
        const int unitBase = r0 * HD;
        const int nUnits   = (r1 - r0) * HD;
        cudaStreamWaitEvent(s1, eF[c], 0);
        const int threads = nUnits * 4;
        sample_kernel<<<(threads + 255) / 256, blk, 0, s1>>>(
            refpt, oa, (const uint4*)val, (uint4*)core, unitBase, nUnits);
        cudaEventRecord(eS[c], s1);
    }

    // stream 0: out GEMM chunks, gated on eS[c]
    for (int c = 0; c < NCHUNK; c++) {
        const int t0 = TB[c], t1 = TB[c + 1];
        cudaStreamWaitEvent(0, eS[c], 0);
        hgemm_out_kernel<<<dim3(2, t1 - t0), blk, SMEM>>>(core, wout, bout, out, t0);
    }
}